// round 3
// baseline (speedup 1.0000x reference)
#include <cuda_runtime.h>
#include <math_constants.h>
#include <stdint.h>

#define KCODES 512
#define DDIM   64
#define NROW   65536
#define QELEMS 4194304
#define NBLK   148
#define NTHR   256
#define LANES  (NBLK * NTHR)          // 37888
#define P2_ROW0 LANES
#define P2_ROWS (NROW - LANES)        // 27648
#define P2_JOBS (P2_ROWS * 4)         // 110592 (k-quarter jobs)

__device__ double g_partial[NBLK];

// smem: codebook 131072 B + norms 2048 B + reduce 2048 B
#define SMEM_BYTES (KCODES * DDIM * 4 + KCODES * 4 + NTHR * 8)

// ---------------------------------------------------------------------------
// Zero a contiguous run of encoding rows; handles the 4-byte phase offset of
// the enc region (d_out+4+QELEMS*4 is not 16B aligned) with scalar fringes.
// ---------------------------------------------------------------------------
__device__ __forceinline__ void zero_rows(float* __restrict__ enc,
                                          int row0, int nrows, int tid) {
    float* p = enc + (size_t)row0 * KCODES;
    int n = nrows * KCODES;
    uintptr_t a = (uintptr_t)p;
    int head = (int)((((a + 15) & ~(uintptr_t)15) - a) >> 2);   // 0..3 floats
    if (tid < head) p[tid] = 0.0f;
    int n4 = (n - head) >> 2;
    int tail = (n - head) & 3;
    float4* v = (float4*)(p + head);
    float4 z = make_float4(0.f, 0.f, 0.f, 0.f);
    for (int i = tid; i < n4; i += NTHR) v[i] = z;
    if (tid >= 4 && tid - 4 < tail) p[head + 4 * n4 + (tid - 4)] = 0.0f;
}

// ---------------------------------------------------------------------------
// Fused kernel: codebook stage + enc zero-fill + norms + argmin (2 phases)
// + q_out + one-hot ones + loss partials.
// ---------------------------------------------------------------------------
__global__ void __launch_bounds__(NTHR) vq_fused(
    const float* __restrict__ x,
    const float* __restrict__ w,
    float* __restrict__ qout,
    float* __restrict__ enc)
{
    extern __shared__ float sm[];
    float*  sw   = sm;                       // [512*64]
    float*  sb   = sm + KCODES * DDIM;       // [512]
    double* sred = (double*)(sb + KCODES);   // [256]

    const int tid  = threadIdx.x;
    const int bid  = blockIdx.x;
    const int gtid = bid * NTHR + tid;

    // Stage codebook (coalesced float4; w is harness-aligned)
    {
        const float4* w4 = (const float4*)w;
        float4*       s4 = (float4*)sw;
        for (int i = tid; i < KCODES * DDIM / 4; i += NTHR) s4[i] = w4[i];
    }

    // Zero-fill exactly the enc rows this block will later write ones into.
    // Stores drain to DRAM while the FFMA loop runs.
    zero_rows(enc, bid * 256, 256, tid);                       // phase-1 rows
    zero_rows(enc, P2_ROW0 +          bid * 64, 64, tid);      // phase-2 it=0
    zero_rows(enc, P2_ROW0 +  9472 +  bid * 64, 64, tid);      // phase-2 it=1
    if (bid < 136)
        zero_rows(enc, P2_ROW0 + 18944 + bid * 64, 64, tid);   // phase-2 it=2
    __syncthreads();   // orders zeros before the one-stores below (block scope)

    // Codebook norms from smem copy — identical rounding chain to reference
    for (int k = tid; k < KCODES; k += NTHR) {
        float acc = 0.0f;
        #pragma unroll
        for (int d = 0; d < DDIM; d++) {
            float v = sw[k * DDIM + d];
            acc = __fadd_rn(acc, __fmul_rn(v, v));
        }
        sb[k] = acc;
    }
    __syncthreads();

    double ls = 0.0;

    // ---------------- Phase 1: one full row per lane -----------------------
    {
        const int n = gtid;                  // < 37888 <= NROW always
        const int b = n >> 10, hw = n & 1023;
        const float* p = x + (size_t)b * 65536 + hw;
        float xr[DDIM];
        #pragma unroll
        for (int d = 0; d < DDIM; d++) xr[d] = p[d * 1024];

        float a = 0.0f;
        #pragma unroll
        for (int d = 0; d < DDIM; d++)
            a = __fadd_rn(a, __fmul_rn(xr[d], xr[d]));

        float best = CUDART_INF_F; int bi = 0;
        for (int k0 = 0; k0 < KCODES; k0 += 2) {
            const float4* w0 = (const float4*)(sw + (k0 << 6));
            float ma = 0.0f, mb = 0.0f;
            #pragma unroll
            for (int j = 0; j < 16; j++) {
                float4 u = w0[j];        // code k0
                float4 v = w0[j + 16];   // code k0+1
                ma = __fmaf_rn(xr[4*j+0], u.x, ma);
                ma = __fmaf_rn(xr[4*j+1], u.y, ma);
                ma = __fmaf_rn(xr[4*j+2], u.z, ma);
                ma = __fmaf_rn(xr[4*j+3], u.w, ma);
                mb = __fmaf_rn(xr[4*j+0], v.x, mb);
                mb = __fmaf_rn(xr[4*j+1], v.y, mb);
                mb = __fmaf_rn(xr[4*j+2], v.z, mb);
                mb = __fmaf_rn(xr[4*j+3], v.w, mb);
            }
            float d0 = __fsub_rn(__fadd_rn(a, sb[k0]),     __fmul_rn(2.0f, ma));
            float d1 = __fsub_rn(__fadd_rn(a, sb[k0 + 1]), __fmul_rn(2.0f, mb));
            if (d0 < best) { best = d0; bi = k0; }
            if (d1 < best) { best = d1; bi = k0 + 1; }
        }

        float* qp = qout + (size_t)b * 65536 + hw;
        const float* wq = sw + bi * DDIM;
        #pragma unroll
        for (int d = 0; d < DDIM; d++) {
            float diff = __fsub_rn(wq[d], xr[d]);
            qp[d * 1024] = __fadd_rn(xr[d], diff);   // straight-through
            ls += (double)__fmul_rn(diff, diff);
        }
        enc[(size_t)n * KCODES + bi] = 1.0f;
    }

    // -------- Phase 2: remaining rows, k split 4-ways across a lane quad ---
    for (int it = 0; it < 3; it++) {
        int j = gtid + it * LANES;
        if (j >= P2_JOBS) break;             // 110592 % 32 == 0: warp-uniform
        const int n = P2_ROW0 + (j >> 2);
        const int q = j & 3;                 // quarter index within lane quad
        const int b = n >> 10, hw = n & 1023;
        const float* p = x + (size_t)b * 65536 + hw;
        float xr[DDIM];
        #pragma unroll
        for (int d = 0; d < DDIM; d++) xr[d] = p[d * 1024];

        float a = 0.0f;
        #pragma unroll
        for (int d = 0; d < DDIM; d++)
            a = __fadd_rn(a, __fmul_rn(xr[d], xr[d]));

        float best = CUDART_INF_F; int bi = 0;
        const int kbase = q * 128;
        for (int kk = 0; kk < 128; kk += 2) {
            int k0 = kbase + kk;
            const float4* w0 = (const float4*)(sw + (k0 << 6));
            float ma = 0.0f, mb = 0.0f;
            #pragma unroll
            for (int jj = 0; jj < 16; jj++) {
                float4 u = w0[jj];
                float4 v = w0[jj + 16];
                ma = __fmaf_rn(xr[4*jj+0], u.x, ma);
                ma = __fmaf_rn(xr[4*jj+1], u.y, ma);
                ma = __fmaf_rn(xr[4*jj+2], u.z, ma);
                ma = __fmaf_rn(xr[4*jj+3], u.w, ma);
                mb = __fmaf_rn(xr[4*jj+0], v.x, mb);
                mb = __fmaf_rn(xr[4*jj+1], v.y, mb);
                mb = __fmaf_rn(xr[4*jj+2], v.z, mb);
                mb = __fmaf_rn(xr[4*jj+3], v.w, mb);
            }
            float d0 = __fsub_rn(__fadd_rn(a, sb[k0]),     __fmul_rn(2.0f, ma));
            float d1 = __fsub_rn(__fadd_rn(a, sb[k0 + 1]), __fmul_rn(2.0f, mb));
            if (d0 < best) { best = d0; bi = k0; }
            if (d1 < best) { best = d1; bi = k0 + 1; }
        }

        // Exact argmin merge across the 4 quarters (ties -> smallest k,
        // i.e. global first-index semantics, identical to a full 512 scan).
        #pragma unroll
        for (int m = 1; m <= 2; m <<= 1) {
            float od = __shfl_xor_sync(0xffffffffu, best, m);
            int   ok = __shfl_xor_sync(0xffffffffu, bi,   m);
            if (od < best || (od == best && ok < bi)) { best = od; bi = ok; }
        }

        if (q == 0) {
            float* qp = qout + (size_t)b * 65536 + hw;
            const float* wq = sw + bi * DDIM;
            #pragma unroll
            for (int d = 0; d < DDIM; d++) {
                float diff = __fsub_rn(wq[d], xr[d]);
                qp[d * 1024] = __fadd_rn(xr[d], diff);
                ls += (double)__fmul_rn(diff, diff);
            }
            enc[(size_t)n * KCODES + bi] = 1.0f;
        }
    }

    // Deterministic block-level loss reduction (fixed tree)
    sred[tid] = ls;
    __syncthreads();
    for (int s = NTHR / 2; s > 0; s >>= 1) {
        if (tid < s) sred[tid] += sred[tid + s];
        __syncthreads();
    }
    if (tid == 0) g_partial[bid] = sred[0];
}

// ---------------------------------------------------------------------------
// Final loss: fixed-tree reduce 148 partials, scale, combine.
// ---------------------------------------------------------------------------
__global__ void loss_final(float* __restrict__ out) {
    __shared__ double sr[256];
    int t = threadIdx.x;
    sr[t] = (t < NBLK) ? g_partial[t] : 0.0;
    __syncthreads();
    for (int s = 128; s > 0; s >>= 1) {
        if (t < s) sr[t] += sr[t + s];
        __syncthreads();
    }
    if (t == 0) {
        float m = (float)(sr[0] / (double)QELEMS);
        out[0] = __fadd_rn(m, __fmul_rn(0.25f, m));   // z_q + 0.25 * z_e
    }
}

// ---------------------------------------------------------------------------
extern "C" void kernel_launch(void* const* d_in, const int* in_sizes, int n_in,
                              void* d_out, int out_size) {
    const float* x = (const float*)d_in[0];   // [64,64,32,32] fp32
    const float* w = (const float*)d_in[1];   // [512,64] fp32
    float* out  = (float*)d_out;
    float* qout = out + 1;                    // [4194304] (4B-aligned only)
    float* enc  = out + 1 + QELEMS;           // [65536*512] (4B-aligned only)

    cudaFuncSetAttribute(vq_fused, cudaFuncAttributeMaxDynamicSharedMemorySize,
                         SMEM_BYTES);

    vq_fused<<<NBLK, NTHR, SMEM_BYTES>>>(x, w, qout, enc);
    loss_final<<<1, 256>>>(out);
}

// round 4
// speedup vs baseline: 3.3258x; 3.3258x over previous
#include <cuda_runtime.h>
#include <math_constants.h>
#include <stdint.h>

#define KCODES 512
#define DDIM   64
#define NROW   65536
#define QELEMS 4194304
#define NBLK   128
#define NTHR   256
#define ROWS_PER_BLOCK 512   // 2 rows per thread

__device__ double g_partial[NBLK];

// smem: codebook 131072 B + norms 2048 B + reduce 2048 B = 135168 B
#define SMEM_BYTES (KCODES * DDIM * 4 + KCODES * 4 + NTHR * 8)

// ---------------------------------------------------------------------------
// Zero this block's 512 encoding rows (1 MB), handling the 4-byte phase offset
// of the enc region with scalar fringes. Stores drain during the FFMA loop.
// ---------------------------------------------------------------------------
__device__ __forceinline__ void zero_rows(float* __restrict__ enc,
                                          int row0, int nrows, int tid) {
    float* p = enc + (size_t)row0 * KCODES;
    int n = nrows * KCODES;
    uintptr_t a = (uintptr_t)p;
    int head = (int)((((a + 15) & ~(uintptr_t)15) - a) >> 2);   // 0..3 floats
    if (tid < head) p[tid] = 0.0f;
    int n4 = (n - head) >> 2;
    int tail = (n - head) & 3;
    float4* v = (float4*)(p + head);
    float4 z = make_float4(0.f, 0.f, 0.f, 0.f);
    for (int i = tid; i < n4; i += NTHR) v[i] = z;
    if (tid >= 4 && tid - 4 < tail) p[head + 4 * n4 + (tid - 4)] = 0.0f;
}

// ---------------------------------------------------------------------------
// Fused: codebook stage + enc zero-fill + norms + argmin + q_out + one-hot
// + loss partials. 2 rows/thread, k-unroll x2 => 4 independent FFMA chains.
// ---------------------------------------------------------------------------
__global__ void __launch_bounds__(NTHR) vq_fused(
    const float* __restrict__ x,
    const float* __restrict__ w,
    float* __restrict__ qout,
    float* __restrict__ enc)
{
    extern __shared__ float sm[];
    float*  sw   = sm;                       // [512*64]
    float*  sb   = sm + KCODES * DDIM;       // [512]
    double* sred = (double*)(sb + KCODES);   // [256]

    const int tid = threadIdx.x;
    const int bid = blockIdx.x;

    // Stage codebook (coalesced float4; w is harness-aligned)
    {
        const float4* w4 = (const float4*)w;
        float4*       s4 = (float4*)sw;
        for (int i = tid; i < KCODES * DDIM / 4; i += NTHR) s4[i] = w4[i];
    }

    // Zero-fill exactly the 512 enc rows this block later writes ones into.
    zero_rows(enc, bid * ROWS_PER_BLOCK, ROWS_PER_BLOCK, tid);

    __syncthreads();   // codebook visible; zeros ordered before ones (block scope)

    // Codebook norms — identical rounding chain to reference
    for (int k = tid; k < KCODES; k += NTHR) {
        float acc = 0.0f;
        #pragma unroll
        for (int d = 0; d < DDIM; d++) {
            float v = sw[k * DDIM + d];
            acc = __fadd_rn(acc, __fmul_rn(v, v));
        }
        sb[k] = acc;
    }
    __syncthreads();

    const int n0 = bid * ROWS_PER_BLOCK + tid;
    const int n1 = n0 + NTHR;

    // x layout [B=64, D=64, H=32, W=32]; row n=(b*32+h)*32+w gathers stride-1024
    float xr0[DDIM], xr1[DDIM];
    {
        int b = n0 >> 10, hw = n0 & 1023;
        const float* p = x + (size_t)b * 65536 + hw;
        #pragma unroll
        for (int d = 0; d < DDIM; d++) xr0[d] = p[d * 1024];
    }
    {
        int b = n1 >> 10, hw = n1 & 1023;
        const float* p = x + (size_t)b * 65536 + hw;
        #pragma unroll
        for (int d = 0; d < DDIM; d++) xr1[d] = p[d * 1024];
    }

    // a = sum(x*x), fp32 sequential, products rounded separately (no FMA)
    float a0 = 0.0f, a1 = 0.0f;
    #pragma unroll
    for (int d = 0; d < DDIM; d++) {
        a0 = __fadd_rn(a0, __fmul_rn(xr0[d], xr0[d]));
        a1 = __fadd_rn(a1, __fmul_rn(xr1[d], xr1[d]));
    }

    float best0 = CUDART_INF_F, best1 = CUDART_INF_F;
    int   bi0 = 0, bi1 = 0;

    // Main loop: 2 codes x 2 rows = 4 independent FMA chains, broadcast LDS
    for (int k0 = 0; k0 < KCODES; k0 += 2) {
        const float4* w0 = (const float4*)(sw + (k0 << 6));
        float ma0 = 0.0f, mb0 = 0.0f, ma1 = 0.0f, mb1 = 0.0f;
        #pragma unroll
        for (int j = 0; j < 16; j++) {
            float4 u = w0[j];        // code k0
            float4 v = w0[j + 16];   // code k0+1
            ma0 = __fmaf_rn(xr0[4*j+0], u.x, ma0);
            ma0 = __fmaf_rn(xr0[4*j+1], u.y, ma0);
            ma0 = __fmaf_rn(xr0[4*j+2], u.z, ma0);
            ma0 = __fmaf_rn(xr0[4*j+3], u.w, ma0);
            mb0 = __fmaf_rn(xr0[4*j+0], v.x, mb0);
            mb0 = __fmaf_rn(xr0[4*j+1], v.y, mb0);
            mb0 = __fmaf_rn(xr0[4*j+2], v.z, mb0);
            mb0 = __fmaf_rn(xr0[4*j+3], v.w, mb0);
            ma1 = __fmaf_rn(xr1[4*j+0], u.x, ma1);
            ma1 = __fmaf_rn(xr1[4*j+1], u.y, ma1);
            ma1 = __fmaf_rn(xr1[4*j+2], u.z, ma1);
            ma1 = __fmaf_rn(xr1[4*j+3], u.w, ma1);
            mb1 = __fmaf_rn(xr1[4*j+0], v.x, mb1);
            mb1 = __fmaf_rn(xr1[4*j+1], v.y, mb1);
            mb1 = __fmaf_rn(xr1[4*j+2], v.z, mb1);
            mb1 = __fmaf_rn(xr1[4*j+3], v.w, mb1);
        }
        float b0 = sb[k0], b1 = sb[k0 + 1];
        // d = fl( fl(a + b) - fl(2*m) ) — exact reference rounding structure
        float d00 = __fsub_rn(__fadd_rn(a0, b0), __fmul_rn(2.0f, ma0));
        float d01 = __fsub_rn(__fadd_rn(a0, b1), __fmul_rn(2.0f, mb0));
        float d10 = __fsub_rn(__fadd_rn(a1, b0), __fmul_rn(2.0f, ma1));
        float d11 = __fsub_rn(__fadd_rn(a1, b1), __fmul_rn(2.0f, mb1));
        if (d00 < best0) { best0 = d00; bi0 = k0; }      // strict <: first index
        if (d01 < best0) { best0 = d01; bi0 = k0 + 1; }
        if (d10 < best1) { best1 = d10; bi1 = k0; }
        if (d11 < best1) { best1 = d11; bi1 = k0 + 1; }
    }

    // Epilogue: straight-through q_out (bit-replicated) + loss + one-hot ones
    double ls = 0.0;
    {
        int b = n0 >> 10, hw = n0 & 1023;
        float* qp = qout + (size_t)b * 65536 + hw;
        const float* wq = sw + bi0 * DDIM;
        #pragma unroll
        for (int d = 0; d < DDIM; d++) {
            float diff = __fsub_rn(wq[d], xr0[d]);
            qp[d * 1024] = __fadd_rn(xr0[d], diff);
            ls += (double)__fmul_rn(diff, diff);
        }
        enc[(size_t)n0 * KCODES + bi0] = 1.0f;
    }
    {
        int b = n1 >> 10, hw = n1 & 1023;
        float* qp = qout + (size_t)b * 65536 + hw;
        const float* wq = sw + bi1 * DDIM;
        #pragma unroll
        for (int d = 0; d < DDIM; d++) {
            float diff = __fsub_rn(wq[d], xr1[d]);
            qp[d * 1024] = __fadd_rn(xr1[d], diff);
            ls += (double)__fmul_rn(diff, diff);
        }
        enc[(size_t)n1 * KCODES + bi1] = 1.0f;
    }

    // Deterministic block-level loss reduction (fixed tree)
    sred[tid] = ls;
    __syncthreads();
    for (int s = NTHR / 2; s > 0; s >>= 1) {
        if (tid < s) sred[tid] += sred[tid + s];
        __syncthreads();
    }
    if (tid == 0) g_partial[bid] = sred[0];
}

// ---------------------------------------------------------------------------
// Final loss: fixed-tree reduce 128 partials, scale, combine.
// ---------------------------------------------------------------------------
__global__ void loss_final(float* __restrict__ out) {
    __shared__ double sr[128];
    int t = threadIdx.x;
    sr[t] = g_partial[t];
    __syncthreads();
    for (int s = 64; s > 0; s >>= 1) {
        if (t < s) sr[t] += sr[t + s];
        __syncthreads();
    }
    if (t == 0) {
        float m = (float)(sr[0] / (double)QELEMS);
        out[0] = __fadd_rn(m, __fmul_rn(0.25f, m));   // z_q + 0.25 * z_e
    }
}

// ---------------------------------------------------------------------------
extern "C" void kernel_launch(void* const* d_in, const int* in_sizes, int n_in,
                              void* d_out, int out_size) {
    const float* x = (const float*)d_in[0];   // [64,64,32,32] fp32
    const float* w = (const float*)d_in[1];   // [512,64] fp32
    float* out  = (float*)d_out;
    float* qout = out + 1;                    // [4194304] (4B-aligned only)
    float* enc  = out + 1 + QELEMS;           // [65536*512] (4B-aligned only)

    cudaFuncSetAttribute(vq_fused, cudaFuncAttributeMaxDynamicSharedMemorySize,
                         SMEM_BYTES);

    vq_fused<<<NBLK, NTHR, SMEM_BYTES>>>(x, w, qout, enc);
    loss_final<<<1, 128>>>(out);
}